// round 1
// baseline (speedup 1.0000x reference)
#include <cuda_runtime.h>

// VQActivation: depth=4 residual VQ.
//   x: [32,256,56,56] fp32   cb: [1024,256] fp32 (unit rows)   out: same as x
// Per depth: ip = resid @ cb^T ; code = argmax ; u = max ; resid -= cb[code]*u
// Output = x - resid_final  (since acc + resid == x invariantly).

#define BATCH  32
#define CDIM   256
#define HW     3136         // 56*56
#define NROWS  100352       // 32*3136
#define KSNUM  1024
#define DEPTH  4

#define TM     128          // rows per CTA
#define TN     128          // codes per tile
#define NTILES (KSNUM/TN)   // 8
#define KC     32           // k-chunk for B streaming

#define AS_F   (CDIM*TM)    // 32768 floats: A tile [k][row]
#define BS_LD  132          // padded lead dim for B tile
#define BS_F   (KC*BS_LD)   // 4224 floats
#define SMEM_F (AS_F + BS_F + TM + TM)
#define SMEM_BYTES (SMEM_F*4)

// persistent residual scratch (102.8 MB) — __device__ global per allocation rules
__device__ float g_resid[(size_t)NROWS * CDIM];

__global__ void __launch_bounds__(256, 1)
vq_step(const float* __restrict__ x,
        const float* __restrict__ cb,
        float* __restrict__ out,
        int iter)
{
    extern __shared__ float sm[];
    float* As    = sm;                        // [CDIM][TM]
    float* Bs    = sm + AS_F;                 // [KC][BS_LD]
    float* su    = sm + AS_F + BS_F;          // [TM]
    int*   scode = (int*)(su + TM);           // [TM]
    // reduction scratch reuses Bs after the main loop:
    float* redM  = Bs;                        // [TM][16]
    int*   redI  = (int*)(Bs + TM*16);        // [TM][16]

    const float* src = (iter == 0) ? x : g_resid;
    const int last = (iter == DEPTH - 1);

    const int tid = threadIdx.x;
    const int tx  = tid & 15;       // code sub-block
    const int ty  = tid >> 4;       // row  sub-block
    const int n0  = blockIdx.x * TM;

    // ---- Phase 1: load A tile [128 rows][256 ch] into smem, k-major ----
    for (int idx = tid; idx < AS_F; idx += 256) {
        int c = idx >> 7;          // channel
        int r = idx & 127;         // row in tile
        int n = n0 + r;
        int b = n / HW;
        int hw = n - b * HW;
        As[c * TM + r] = src[(size_t)b * (CDIM * HW) + (size_t)c * HW + hw];
    }
    __syncthreads();

    float rmax[8];
    int   ridx[8];
#pragma unroll
    for (int i = 0; i < 8; i++) { rmax[i] = -3.0e38f; ridx[i] = 0; }

    const float4* cb4 = (const float4*)cb;

    // ---- Phase 2: 8 code tiles x full-K GEMM with fused running argmax ----
    for (int ct = 0; ct < NTILES; ct++) {
        float acc[8][8];
#pragma unroll
        for (int i = 0; i < 8; i++)
#pragma unroll
            for (int j = 0; j < 8; j++) acc[i][j] = 0.0f;

        for (int kc = 0; kc < CDIM; kc += KC) {
            __syncthreads();
            // load B chunk: codes [ct*128, +128), k in [kc, kc+32), transposed
#pragma unroll
            for (int q = 0; q < 4; q++) {
                int j  = tid * 4 + q;     // 0..1023
                int cl = j >> 3;          // code_local 0..127
                int kq = j & 7;           // float4 index within chunk
                float4 v = cb4[(size_t)(ct * TN + cl) * (CDIM / 4) + (kc >> 2) + kq];
                int kk = kq * 4;
                Bs[(kk + 0) * BS_LD + cl] = v.x;
                Bs[(kk + 1) * BS_LD + cl] = v.y;
                Bs[(kk + 2) * BS_LD + cl] = v.z;
                Bs[(kk + 3) * BS_LD + cl] = v.w;
            }
            __syncthreads();

#pragma unroll
            for (int k = 0; k < KC; k++) {
                float a[8], bb[8];
                const float* ap = &As[(kc + k) * TM + ty * 8];
                *(float4*)&a[0] = *(const float4*)(ap);
                *(float4*)&a[4] = *(const float4*)(ap + 4);
                const float* bp = &Bs[k * BS_LD + tx * 8];
                *(float4*)&bb[0] = *(const float4*)(bp);
                *(float4*)&bb[4] = *(const float4*)(bp + 4);
#pragma unroll
                for (int i = 0; i < 8; i++)
#pragma unroll
                    for (int j = 0; j < 8; j++)
                        acc[i][j] = fmaf(a[i], bb[j], acc[i][j]);
            }
        }

        // fold this code tile into running per-row (max, argmax)
#pragma unroll
        for (int i = 0; i < 8; i++)
#pragma unroll
            for (int j = 0; j < 8; j++) {
                int code = ct * TN + tx * 8 + j;
                float v = acc[i][j];
                if (v > rmax[i] || (v == rmax[i] && code < ridx[i])) {
                    rmax[i] = v; ridx[i] = code;
                }
            }
    }

    // ---- Phase 3: cross-thread argmax reduction (16 partials per row) ----
    __syncthreads();                       // done with Bs -> reuse as scratch
#pragma unroll
    for (int i = 0; i < 8; i++) {
        int r = ty * 8 + i;
        redM[r * 16 + tx] = rmax[i];
        redI[r * 16 + tx] = ridx[i];
    }
    __syncthreads();
    if (tid < TM) {
        int r = tid;
        float best = redM[r * 16];
        int   bi   = redI[r * 16];
#pragma unroll
        for (int t = 1; t < 16; t++) {
            float v = redM[r * 16 + t];
            int  ii = redI[r * 16 + t];
            if (v > best || (v == best && ii < bi)) { best = v; bi = ii; }
        }
        su[r]    = best;
        scode[r] = bi;
    }
    __syncthreads();

    // ---- Phase 4: resid update (and output on last depth) ----
#pragma unroll 2
    for (int idx = tid; idx < AS_F; idx += 256) {
        int c = idx >> 7;
        int r = idx & 127;
        float val = As[c * TM + r] - su[r] * cb[(size_t)scode[r] * CDIM + c];
        int n = n0 + r;
        int b = n / HW;
        int hw = n - b * HW;
        size_t g = (size_t)b * (CDIM * HW) + (size_t)c * HW + hw;
        if (last) out[g] = x[g] - val;
        else      g_resid[g] = val;
    }
}

extern "C" void kernel_launch(void* const* d_in, const int* in_sizes, int n_in,
                              void* d_out, int out_size)
{
    const float* x  = (const float*)d_in[0];
    const float* cb = (const float*)d_in[1];
    float* out = (float*)d_out;

    cudaFuncSetAttribute(vq_step, cudaFuncAttributeMaxDynamicSharedMemorySize,
                         SMEM_BYTES);

    dim3 grid(NROWS / TM);   // 784
    dim3 block(256);
    for (int it = 0; it < DEPTH; it++) {
        vq_step<<<grid, block, SMEM_BYTES>>>(x, cb, out, it);
    }
}

// round 2
// speedup vs baseline: 1.0008x; 1.0008x over previous
#include <cuda_runtime.h>

// VQActivation: depth=4 residual VQ.
//   x: [32,256,56,56] fp32   cb: [1024,256] fp32 (unit rows)   out: same as x
// Per depth: ip = resid @ cb^T ; code = argmax ; u = max ; resid -= cb[code]*u
// Output = x - resid_final  (since acc + resid == x invariantly).

#define BATCH  32
#define CDIM   256
#define HW     3136         // 56*56
#define NROWS  100352       // 32*3136
#define KSNUM  1024
#define DEPTH  4

#define TM     128          // rows per CTA
#define TN     128          // codes per tile
#define NTILES (KSNUM/TN)   // 8
#define KC     32           // k-chunk for B streaming

#define AS_F   (CDIM*TM)    // 32768 floats: A tile [k][row]
#define BS_LD  132          // padded lead dim for B tile
#define BS_F   (KC*BS_LD)   // 4224 floats
#define SMEM_F (AS_F + BS_F + TM + TM)
#define SMEM_BYTES (SMEM_F*4)

// persistent residual scratch (102.8 MB) — __device__ global per allocation rules
__device__ float g_resid[(size_t)NROWS * CDIM];

__global__ void __launch_bounds__(256, 1)
vq_step(const float* __restrict__ x,
        const float* __restrict__ cb,
        float* __restrict__ out,
        int iter)
{
    extern __shared__ float sm[];
    float* As    = sm;                        // [CDIM][TM]
    float* Bs    = sm + AS_F;                 // [KC][BS_LD]
    float* su    = sm + AS_F + BS_F;          // [TM]
    int*   scode = (int*)(su + TM);           // [TM]
    // reduction scratch reuses Bs after the main loop:
    float* redM  = Bs;                        // [TM][16]
    int*   redI  = (int*)(Bs + TM*16);        // [TM][16]

    const float* src = (iter == 0) ? x : g_resid;
    const int last = (iter == DEPTH - 1);

    const int tid = threadIdx.x;
    const int tx  = tid & 15;       // code sub-block
    const int ty  = tid >> 4;       // row  sub-block
    const int n0  = blockIdx.x * TM;

    // ---- Phase 1: load A tile [128 rows][256 ch] into smem, k-major ----
    for (int idx = tid; idx < AS_F; idx += 256) {
        int c = idx >> 7;          // channel
        int r = idx & 127;         // row in tile
        int n = n0 + r;
        int b = n / HW;
        int hw = n - b * HW;
        As[c * TM + r] = src[(size_t)b * (CDIM * HW) + (size_t)c * HW + hw];
    }
    __syncthreads();

    float rmax[8];
    int   ridx[8];
#pragma unroll
    for (int i = 0; i < 8; i++) { rmax[i] = -3.0e38f; ridx[i] = 0; }

    const float4* cb4 = (const float4*)cb;

    // ---- Phase 2: 8 code tiles x full-K GEMM with fused running argmax ----
    for (int ct = 0; ct < NTILES; ct++) {
        float acc[8][8];
#pragma unroll
        for (int i = 0; i < 8; i++)
#pragma unroll
            for (int j = 0; j < 8; j++) acc[i][j] = 0.0f;

        for (int kc = 0; kc < CDIM; kc += KC) {
            __syncthreads();
            // load B chunk: codes [ct*128, +128), k in [kc, kc+32), transposed
#pragma unroll
            for (int q = 0; q < 4; q++) {
                int j  = tid * 4 + q;     // 0..1023
                int cl = j >> 3;          // code_local 0..127
                int kq = j & 7;           // float4 index within chunk
                float4 v = cb4[(size_t)(ct * TN + cl) * (CDIM / 4) + (kc >> 2) + kq];
                int kk = kq * 4;
                Bs[(kk + 0) * BS_LD + cl] = v.x;
                Bs[(kk + 1) * BS_LD + cl] = v.y;
                Bs[(kk + 2) * BS_LD + cl] = v.z;
                Bs[(kk + 3) * BS_LD + cl] = v.w;
            }
            __syncthreads();

#pragma unroll
            for (int k = 0; k < KC; k++) {
                float a[8], bb[8];
                const float* ap = &As[(kc + k) * TM + ty * 8];
                *(float4*)&a[0] = *(const float4*)(ap);
                *(float4*)&a[4] = *(const float4*)(ap + 4);
                const float* bp = &Bs[k * BS_LD + tx * 8];
                *(float4*)&bb[0] = *(const float4*)(bp);
                *(float4*)&bb[4] = *(const float4*)(bp + 4);
#pragma unroll
                for (int i = 0; i < 8; i++)
#pragma unroll
                    for (int j = 0; j < 8; j++)
                        acc[i][j] = fmaf(a[i], bb[j], acc[i][j]);
            }
        }

        // fold this code tile into running per-row (max, argmax)
#pragma unroll
        for (int i = 0; i < 8; i++)
#pragma unroll
            for (int j = 0; j < 8; j++) {
                int code = ct * TN + tx * 8 + j;
                float v = acc[i][j];
                if (v > rmax[i] || (v == rmax[i] && code < ridx[i])) {
                    rmax[i] = v; ridx[i] = code;
                }
            }
    }

    // ---- Phase 3: cross-thread argmax reduction (16 partials per row) ----
    __syncthreads();                       // done with Bs -> reuse as scratch
#pragma unroll
    for (int i = 0; i < 8; i++) {
        int r = ty * 8 + i;
        redM[r * 16 + tx] = rmax[i];
        redI[r * 16 + tx] = ridx[i];
    }
    __syncthreads();
    if (tid < TM) {
        int r = tid;
        float best = redM[r * 16];
        int   bi   = redI[r * 16];
#pragma unroll
        for (int t = 1; t < 16; t++) {
            float v = redM[r * 16 + t];
            int  ii = redI[r * 16 + t];
            if (v > best || (v == best && ii < bi)) { best = v; bi = ii; }
        }
        su[r]    = best;
        scode[r] = bi;
    }
    __syncthreads();

    // ---- Phase 4: resid update (and output on last depth) ----
#pragma unroll 2
    for (int idx = tid; idx < AS_F; idx += 256) {
        int c = idx >> 7;
        int r = idx & 127;
        float val = As[c * TM + r] - su[r] * cb[(size_t)scode[r] * CDIM + c];
        int n = n0 + r;
        int b = n / HW;
        int hw = n - b * HW;
        size_t g = (size_t)b * (CDIM * HW) + (size_t)c * HW + hw;
        if (last) out[g] = x[g] - val;
        else      g_resid[g] = val;
    }
}

extern "C" void kernel_launch(void* const* d_in, const int* in_sizes, int n_in,
                              void* d_out, int out_size)
{
    const float* x  = (const float*)d_in[0];
    const float* cb = (const float*)d_in[1];
    float* out = (float*)d_out;

    cudaFuncSetAttribute(vq_step, cudaFuncAttributeMaxDynamicSharedMemorySize,
                         SMEM_BYTES);

    dim3 grid(NROWS / TM);   // 784
    dim3 block(256);
    for (int it = 0; it < DEPTH; it++) {
        vq_step<<<grid, block, SMEM_BYTES>>>(x, cb, out, it);
    }
}

// round 8
// speedup vs baseline: 1.5842x; 1.5829x over previous
#include <cuda_runtime.h>
#include <cstdint>

// VQActivation depth-4 residual VQ.
// tf32 mma.sync ranking (top-4) + serial-fp32 rescoring that bitwise-matches
// the reference's cuBLAS-style fp32 accumulation, so argmax decisions and the
// residual chain replicate the reference exactly.
#define CDIM  256
#define HW    3136
#define NROWS 100352
#define DEPTH 4
#define TM    128
#define TAU   0.006f

#define AS_STRIDE 136               // floats; conflict-free fragment loads
#define BS_STRIDE 36
#define OFF_CODE 0                  // 128 ints
#define OFF_SU   512                // 128 floats
#define OFF_A    1024
#define A_BYTES  (CDIM*AS_STRIDE*4)       // 139264
#define OFF_B    (OFF_A + A_BYTES)        // 140288
#define B_BYTES  (128*BS_STRIDE*4)        // 18432
#define SMEM_BYTES (OFF_B + 2*B_BYTES)    // 177152

__device__ float    g_resid[(size_t)NROWS * CDIM];
__device__ uint32_t g_cbt[1024 * CDIM];          // tf32-rounded codebook

__device__ __forceinline__ uint32_t f2tf32(float f) {
    uint32_t u;
    asm("cvt.rna.tf32.f32 %0, %1;" : "=r"(u) : "f"(f));
    return u;
}
__device__ __forceinline__ void mma8(float* d, uint32_t a0, uint32_t a1,
                                     uint32_t a2, uint32_t a3,
                                     uint32_t b0, uint32_t b1) {
    asm volatile("mma.sync.aligned.m16n8k8.row.col.f32.tf32.tf32.f32 "
                 "{%0,%1,%2,%3}, {%4,%5,%6,%7}, {%8,%9}, {%0,%1,%2,%3};"
                 : "+f"(d[0]), "+f"(d[1]), "+f"(d[2]), "+f"(d[3])
                 : "r"(a0), "r"(a1), "r"(a2), "r"(a3), "r"(b0), "r"(b1));
}
#define CP16(sm, gp) asm volatile("cp.async.cg.shared.global [%0], [%1], 16;" :: "r"(sm), "l"(gp))
#define CP_COMMIT()  asm volatile("cp.async.commit_group;")
#define CP_WAIT1()   asm volatile("cp.async.wait_group 1;")
#define CP_WAIT0()   asm volatile("cp.async.wait_group 0;")

__device__ __forceinline__ uint32_t smem_u32(const void* p) {
    uint32_t a;
    asm("{ .reg .u64 t; cvta.to.shared.u64 t, %1; cvt.u32.u64 %0, t; }" : "=r"(a) : "l"(p));
    return a;
}

__global__ void prep_cbt(const float* __restrict__ cb) {
    int i = blockIdx.x * 256 + threadIdx.x;
    g_cbt[i] = f2tf32(cb[i]);
}

__global__ void __launch_bounds__(256, 1)
vq_step(const float* __restrict__ x, const float* __restrict__ cb,
        float* __restrict__ out, int iter)
{
    extern __shared__ char smem[];
    const uint32_t sb = smem_u32(smem);
    float* AsF   = (float*)(smem + OFF_A);
    int*   scode = (int*)(smem + OFF_CODE);
    float* su    = (float*)(smem + OFF_SU);

    const int tid  = threadIdx.x;
    const int lane = tid & 31, w = tid >> 5;
    const int quad = lane >> 2, qt = lane & 3;
    const int wrow = (w >> 1) * 32;       // 0,32,64,96
    const int ncb  = (w & 1) * 64;
    const int n0   = blockIdx.x * TM;
    const float* src = (iter == 0) ? x : g_resid;
    const bool last = (iter == DEPTH - 1);

    // ---- stage A tile [k][row], EXACT fp32, stride 136 ----
    for (int idx = tid; idx < TM * CDIM; idx += 256) {
        int c = idx >> 7, r = idx & 127;
        int n = n0 + r;
        int b = n / HW;
        int hw = n - b * HW;
        AsF[c * AS_STRIDE + r] = src[(size_t)b * (CDIM * HW) + (size_t)c * HW + hw];
    }

    auto prefetch = [&](int g) {   // chunk g: code tile g>>3, k-chunk g&7
        int ct = g >> 3, kc = g & 7;
        const uint32_t* gb = g_cbt + (size_t)(ct * 128) * CDIM + kc * 32;
        uint32_t smb = sb + OFF_B + (uint32_t)(g & 1) * B_BYTES;
#pragma unroll
        for (int q = 0; q < 4; q++) {
            int j = tid + q * 256;
            int cl = j >> 3, kq = j & 7;
            CP16(smb + (uint32_t)(cl * BS_STRIDE + kq * 4) * 4,
                 gb + (size_t)cl * CDIM + kq * 4);
        }
        CP_COMMIT();
    };
    prefetch(0);
    __syncthreads();          // A staged before compute

    float mv[4][4]; int mi[4][4];
#pragma unroll
    for (int i = 0; i < 4; i++)
#pragma unroll
        for (int j = 0; j < 4; j++) { mv[i][j] = -3.0e38f; mi[i][j] = 0; }

    for (int ct = 0; ct < 8; ct++) {
        float acc[16][4];
#pragma unroll
        for (int i = 0; i < 16; i++)
#pragma unroll
            for (int j = 0; j < 4; j++) acc[i][j] = 0.0f;

        for (int kc = 0; kc < 8; kc++) {
            int g = ct * 8 + kc;
            if (g + 1 < 64) { prefetch(g + 1); CP_WAIT1(); }
            else            { CP_WAIT0(); }
            __syncthreads();
            const uint32_t* BsU = (const uint32_t*)(smem + OFF_B + (g & 1) * B_BYTES);
#pragma unroll
            for (int k8 = 0; k8 < 4; k8++) {
                const float* Ap  = AsF + (kc * 32 + k8 * 8 + qt) * AS_STRIDE + wrow + quad;
                const float* Ap2 = Ap + 4 * AS_STRIDE;
                uint32_t a00 = f2tf32(Ap[0]),   a01 = f2tf32(Ap[8]);
                uint32_t a02 = f2tf32(Ap2[0]),  a03 = f2tf32(Ap2[8]);
                uint32_t a10 = f2tf32(Ap[16]),  a11 = f2tf32(Ap[24]);
                uint32_t a12 = f2tf32(Ap2[16]), a13 = f2tf32(Ap2[24]);
#pragma unroll
                for (int nf = 0; nf < 8; nf++) {
                    int code = ncb + nf * 8 + quad;
                    uint32_t b0 = BsU[code * BS_STRIDE + k8 * 8 + qt];
                    uint32_t b1 = BsU[code * BS_STRIDE + k8 * 8 + qt + 4];
                    mma8(acc[nf],     a00, a01, a02, a03, b0, b1);
                    mma8(acc[8 + nf], a10, a11, a12, a13, b0, b1);
                }
            }
            __syncthreads();
        }

        // fold tile into per-thread top-4 (4 owned rows)
#pragma unroll
        for (int nf = 0; nf < 8; nf++)
#pragma unroll
            for (int half = 0; half < 2; half++)
#pragma unroll
                for (int j = 0; j < 4; j++) {
                    float v = acc[half * 8 + nf][j];
                    int lr = half * 2 + (j >> 1);
                    int code = ct * 128 + ncb + nf * 8 + qt * 2 + (j & 1);
                    if (v > mv[lr][0]) {
                        mv[lr][3] = mv[lr][2]; mi[lr][3] = mi[lr][2];
                        mv[lr][2] = mv[lr][1]; mi[lr][2] = mi[lr][1];
                        mv[lr][1] = mv[lr][0]; mi[lr][1] = mi[lr][0];
                        mv[lr][0] = v;         mi[lr][0] = code;
                    } else if (v > mv[lr][1]) {
                        mv[lr][3] = mv[lr][2]; mi[lr][3] = mi[lr][2];
                        mv[lr][2] = mv[lr][1]; mi[lr][2] = mi[lr][1];
                        mv[lr][1] = v;         mi[lr][1] = code;
                    } else if (v > mv[lr][2]) {
                        mv[lr][3] = mv[lr][2]; mi[lr][3] = mi[lr][2];
                        mv[lr][2] = v;         mi[lr][2] = code;
                    } else if (v > mv[lr][3]) {
                        mv[lr][3] = v;         mi[lr][3] = code;
                    }
                }
    }

    // ---- cross-thread merge: 8 partial top-4 sets per row (stride 33) ----
    float* redV = (float*)(smem + OFF_B);
    int*   redI = (int*)(smem + OFF_B + 16896);
    __syncthreads();
#pragma unroll
    for (int lr = 0; lr < 4; lr++) {
        int row = wrow + lr * 8 + quad;
        int slot = (w & 1) * 4 + qt;
#pragma unroll
        for (int j = 0; j < 4; j++) {
            redV[row * 33 + slot * 4 + j] = mv[lr][j];
            redI[row * 33 + slot * 4 + j] = mi[lr][j];
        }
    }
    __syncthreads();

    if (tid < TM) {
        // global top-4 for this row (value desc, index asc on ties)
        float m0 = -3.0e38f, m1 = -3.0e38f, m2 = -3.0e38f, m3 = -3.0e38f;
        int j0 = 0, j1 = 0, j2 = 0, j3 = 0;
#pragma unroll 2
        for (int s = 0; s < 32; s++) {
            float v = redV[tid * 33 + s];
            int   c = redI[tid * 33 + s];
            if (v > m0 || (v == m0 && c < j0)) {
                m3 = m2; j3 = j2; m2 = m1; j2 = j1; m1 = m0; j1 = j0; m0 = v; j0 = c;
            } else if (v > m1 || (v == m1 && c < j1)) {
                m3 = m2; j3 = j2; m2 = m1; j2 = j1; m1 = v; j1 = c;
            } else if (v > m2 || (v == m2 && c < j2)) {
                m3 = m2; j3 = j2; m2 = v; j2 = c;
            } else if (v > m3 || (v == m3 && c < j3)) {
                m3 = v; j3 = c;
            }
        }
        // candidates: pad to j0 when outside tau (dup loads hit L1, no cost)
        int c0i = j0;
        int c1i = (m0 - m1 <= TAU) ? j1 : j0;
        int c2i = (m0 - m2 <= TAU) ? j2 : j0;
        int c3i = (m0 - m3 <= TAU) ? j3 : j0;

        // serial ascending-k fp32 FMA chains — replicates the reference's
        // cuBLAS-style accumulation bitwise. u = winner's serial value.
        const float4* p0 = (const float4*)(cb + (size_t)c0i * CDIM);
        const float4* p1 = (const float4*)(cb + (size_t)c1i * CDIM);
        const float4* p2 = (const float4*)(cb + (size_t)c2i * CDIM);
        const float4* p3 = (const float4*)(cb + (size_t)c3i * CDIM);
        float s0 = 0.0f, s1 = 0.0f, s2 = 0.0f, s3 = 0.0f;
#pragma unroll 4
        for (int q = 0; q < 64; q++) {
            float a0 = AsF[(q * 4 + 0) * AS_STRIDE + tid];
            float a1 = AsF[(q * 4 + 1) * AS_STRIDE + tid];
            float a2 = AsF[(q * 4 + 2) * AS_STRIDE + tid];
            float a3 = AsF[(q * 4 + 3) * AS_STRIDE + tid];
            float4 b0 = __ldg(p0 + q), b1 = __ldg(p1 + q);
            float4 b2 = __ldg(p2 + q), b3 = __ldg(p3 + q);
            s0 = fmaf(a0, b0.x, s0); s0 = fmaf(a1, b0.y, s0);
            s0 = fmaf(a2, b0.z, s0); s0 = fmaf(a3, b0.w, s0);
            s1 = fmaf(a0, b1.x, s1); s1 = fmaf(a1, b1.y, s1);
            s1 = fmaf(a2, b1.z, s1); s1 = fmaf(a3, b1.w, s1);
            s2 = fmaf(a0, b2.x, s2); s2 = fmaf(a1, b2.y, s2);
            s2 = fmaf(a2, b2.z, s2); s2 = fmaf(a3, b2.w, s2);
            s3 = fmaf(a0, b3.x, s3); s3 = fmaf(a1, b3.y, s3);
            s3 = fmaf(a2, b3.z, s3); s3 = fmaf(a3, b3.w, s3);
        }
        float bp = s0; int bi = c0i;
        if (s1 > bp || (s1 == bp && c1i < bi)) { bp = s1; bi = c1i; }
        if (s2 > bp || (s2 == bp && c2i < bi)) { bp = s2; bi = c2i; }
        if (s3 > bp || (s3 == bp && c3i < bi)) { bp = s3; bi = c3i; }
        scode[tid] = bi;
        su[tid]    = bp;
    }

    // ---- epilogue: residual update = resid - cb[code]*u  (mul then sub,
    //      matching the reference bitwise; no fma contraction) ----
    float* cbS = (float*)(smem + OFF_B);     // 32 x 257 floats, reuse B area
    for (int h = 0; h < 4; h++) {
        __syncthreads();
        for (int it = 0; it < 32; it++)      // stage chosen codewords
            cbS[it * 257 + tid] = cb[(size_t)scode[h * 32 + it] * CDIM + tid];
        __syncthreads();
#pragma unroll 4
        for (int it = 0; it < 32; it++) {
            int idx = tid + it * 256;
            int rl = idx & 31, c = idx >> 5;
            int r = h * 32 + rl;
            float val = __fsub_rn(AsF[c * AS_STRIDE + r],
                                  __fmul_rn(su[r], cbS[rl * 257 + c]));
            int n = n0 + r;
            int b = n / HW;
            int hw = n - b * HW;
            size_t gidx = (size_t)b * (CDIM * HW) + (size_t)c * HW + hw;
            if (last) out[gidx] = __fsub_rn(x[gidx], val);
            else      g_resid[gidx] = val;
        }
    }
}

extern "C" void kernel_launch(void* const* d_in, const int* in_sizes, int n_in,
                              void* d_out, int out_size)
{
    const float* x  = (const float*)d_in[0];
    const float* cb = (const float*)d_in[1];
    float* out = (float*)d_out;

    cudaFuncSetAttribute(vq_step, cudaFuncAttributeMaxDynamicSharedMemorySize,
                         SMEM_BYTES);
    prep_cbt<<<1024, 256>>>(cb);
    dim3 grid(NROWS / TM), block(256);
    for (int it = 0; it < DEPTH; it++)
        vq_step<<<grid, block, SMEM_BYTES>>>(x, cb, out, it);
}

// round 10
// speedup vs baseline: 2.0384x; 1.2867x over previous
#include <cuda_runtime.h>
#include <cstdint>

// VQActivation depth-4 residual VQ.
// tf32 mma.sync ranking (pre-converted A, 16 warps, top-2/thread) +
// serial-fp32 rescoring bitwise-matching the reference's accumulation.
#define CDIM  256
#define HW    3136
#define NROWS 100352
#define DEPTH 4
#define TM    128
#define NTH   512
#define TAU   0.006f

#define AS_STRIDE 136
#define BS_STRIDE 36
#define OFF_CODE 0                        // 128 ints
#define OFF_SU   512                      // 128 floats
#define OFF_A    1024
#define A_BYTES  (CDIM*AS_STRIDE*4)       // 139264 (tf32-as-uint)
#define OFF_B    (OFF_A + A_BYTES)        // 140288
#define B_BYTES  (128*BS_STRIDE*4)        // 18432 per buffer, 3 buffers
#define SMEM_BYTES (OFF_B + 3*B_BYTES)    // 195584

__device__ float    g_resid[(size_t)NROWS * CDIM];
__device__ uint32_t g_cbt[1024 * CDIM];          // tf32-rounded codebook

__device__ __forceinline__ uint32_t f2tf32(float f) {
    uint32_t u;
    asm("cvt.rna.tf32.f32 %0, %1;" : "=r"(u) : "f"(f));
    return u;
}
__device__ __forceinline__ void mma8(float* d, uint32_t a0, uint32_t a1,
                                     uint32_t a2, uint32_t a3,
                                     uint32_t b0, uint32_t b1) {
    asm volatile("mma.sync.aligned.m16n8k8.row.col.f32.tf32.tf32.f32 "
                 "{%0,%1,%2,%3}, {%4,%5,%6,%7}, {%8,%9}, {%0,%1,%2,%3};"
                 : "+f"(d[0]), "+f"(d[1]), "+f"(d[2]), "+f"(d[3])
                 : "r"(a0), "r"(a1), "r"(a2), "r"(a3), "r"(b0), "r"(b1));
}
#define CP16(sm, gp) asm volatile("cp.async.cg.shared.global [%0], [%1], 16;" :: "r"(sm), "l"(gp))
#define CP_COMMIT()  asm volatile("cp.async.commit_group;")
#define CP_WAIT1()   asm volatile("cp.async.wait_group 1;")
#define CP_WAIT0()   asm volatile("cp.async.wait_group 0;")

__device__ __forceinline__ uint32_t smem_u32(const void* p) {
    uint32_t a;
    asm("{ .reg .u64 t; cvta.to.shared.u64 t, %1; cvt.u32.u64 %0, t; }" : "=r"(a) : "l"(p));
    return a;
}

__global__ void prep_cbt(const float* __restrict__ cb) {
    int i = blockIdx.x * 256 + threadIdx.x;
    g_cbt[i] = f2tf32(cb[i]);
}

__global__ void __launch_bounds__(NTH, 1)
vq_step(const float* __restrict__ x, const float* __restrict__ cb,
        float* __restrict__ out, int iter)
{
    extern __shared__ char smem[];
    const uint32_t sb = smem_u32(smem);
    uint32_t* AsT   = (uint32_t*)(smem + OFF_A);
    int*      scode = (int*)(smem + OFF_CODE);
    float*    su    = (float*)(smem + OFF_SU);

    const int tid  = threadIdx.x;
    const int lane = tid & 31, w = tid >> 5;
    const int quad = lane >> 2, qt = lane & 3;
    const int wr   = w >> 2;            // row group: rows wr*32..+31
    const int wc   = w & 3;             // col group: codes wc*32..+31 in tile
    const int wrow = wr * 32;
    const int n0   = blockIdx.x * TM;
    const float* src = (iter == 0) ? x : g_resid;
    const bool last = (iter == DEPTH - 1);

    // ---- stage A tile [k][row] as tf32 (exact values re-read from gmem later)
    for (int idx = tid; idx < TM * CDIM; idx += NTH) {
        int c = idx >> 7, r = idx & 127;
        int n = n0 + r;
        int b = n / HW;
        int hw = n - b * HW;
        AsT[c * AS_STRIDE + r] =
            f2tf32(src[(size_t)b * (CDIM * HW) + (size_t)c * HW + hw]);
    }

    auto prefetch = [&](int g, int buf) {   // chunk g: code tile g>>3, k-chunk g&7
        int ct = g >> 3, kc = g & 7;
        const uint32_t* gb = g_cbt + (size_t)(ct * 128) * CDIM + kc * 32;
        uint32_t smb = sb + OFF_B + (uint32_t)buf * B_BYTES;
#pragma unroll
        for (int q = 0; q < 2; q++) {
            int j = tid + q * NTH;          // 0..1023
            int cl = j >> 3, kq = j & 7;
            CP16(smb + (uint32_t)(cl * BS_STRIDE + kq * 4) * 4,
                 gb + (size_t)cl * CDIM + kq * 4);
        }
        CP_COMMIT();
    };
    prefetch(0, 0);
    prefetch(1, 1);

    float mv[4][2]; int mi[4][2];
#pragma unroll
    for (int i = 0; i < 4; i++)
#pragma unroll
        for (int j = 0; j < 2; j++) { mv[i][j] = -3.0e38f; mi[i][j] = 0; }

    int buf = 0;
    for (int ct = 0; ct < 8; ct++) {
        float acc[8][4];
#pragma unroll
        for (int i = 0; i < 8; i++)
#pragma unroll
            for (int j = 0; j < 4; j++) acc[i][j] = 0.0f;

        for (int kc = 0; kc < 8; kc++) {
            int g = ct * 8 + kc;
            if (g == 63) CP_WAIT0(); else CP_WAIT1();
            __syncthreads();               // chunk g visible; buf (g+2)%3 free
            if (g + 2 < 64) {
                int nb = buf + 2; if (nb >= 3) nb -= 3;
                prefetch(g + 2, nb);
            }
            const uint32_t* Bs = (const uint32_t*)(smem + OFF_B + buf * B_BYTES)
                                 + wc * 32 * BS_STRIDE;
#pragma unroll
            for (int k8 = 0; k8 < 4; k8++) {
                const uint32_t* Ap  = AsT + (kc * 32 + k8 * 8 + qt) * AS_STRIDE
                                          + wrow + quad;
                const uint32_t* Ap2 = Ap + 4 * AS_STRIDE;
                uint32_t a00 = Ap[0],   a01 = Ap[8];
                uint32_t a02 = Ap2[0],  a03 = Ap2[8];
                uint32_t a10 = Ap[16],  a11 = Ap[24];
                uint32_t a12 = Ap2[16], a13 = Ap2[24];
#pragma unroll
                for (int cf = 0; cf < 4; cf++) {
                    uint32_t b0 = Bs[(cf * 8 + quad) * BS_STRIDE + k8 * 8 + qt];
                    uint32_t b1 = Bs[(cf * 8 + quad) * BS_STRIDE + k8 * 8 + qt + 4];
                    mma8(acc[cf],     a00, a01, a02, a03, b0, b1);
                    mma8(acc[4 + cf], a10, a11, a12, a13, b0, b1);
                }
            }
            buf++; if (buf >= 3) buf = 0;
        }

        // fold tile into per-thread top-2 (4 owned rows)
#pragma unroll
        for (int cf = 0; cf < 4; cf++)
#pragma unroll
            for (int half = 0; half < 2; half++)
#pragma unroll
                for (int j = 0; j < 4; j++) {
                    float v = acc[half * 4 + cf][j];
                    int lr = half * 2 + (j >> 1);
                    int code = ct * 128 + wc * 32 + cf * 8 + qt * 2 + (j & 1);
                    if (v > mv[lr][0]) {
                        mv[lr][1] = mv[lr][0]; mi[lr][1] = mi[lr][0];
                        mv[lr][0] = v;         mi[lr][0] = code;
                    } else if (v > mv[lr][1]) {
                        mv[lr][1] = v;         mi[lr][1] = code;
                    }
                }
    }

    // ---- merge: 16 partial top-2 sets per row -> smem (stride 33) ----
    float* redV = (float*)(smem + OFF_B);
    int*   redI = (int*)(smem + OFF_B + 16896);
    __syncthreads();
    {
        int slot = wc * 4 + qt;
#pragma unroll
        for (int lr = 0; lr < 4; lr++) {
            int row = wrow + lr * 8 + quad;
            redV[row * 33 + slot * 2 + 0] = mv[lr][0];
            redV[row * 33 + slot * 2 + 1] = mv[lr][1];
            redI[row * 33 + slot * 2 + 0] = mi[lr][0];
            redI[row * 33 + slot * 2 + 1] = mi[lr][1];
        }
    }
    __syncthreads();

    if (tid < TM) {
        float m0 = -3.0e38f, m1 = -3.0e38f, m2 = -3.0e38f, m3 = -3.0e38f;
        int j0 = 0, j1 = 0, j2 = 0, j3 = 0;
#pragma unroll 2
        for (int s = 0; s < 32; s++) {
            float v = redV[tid * 33 + s];
            int   c = redI[tid * 33 + s];
            if (v > m0 || (v == m0 && c < j0)) {
                m3 = m2; j3 = j2; m2 = m1; j2 = j1; m1 = m0; j1 = j0; m0 = v; j0 = c;
            } else if (v > m1 || (v == m1 && c < j1)) {
                m3 = m2; j3 = j2; m2 = m1; j2 = j1; m1 = v; j1 = c;
            } else if (v > m2 || (v == m2 && c < j2)) {
                m3 = m2; j3 = j2; m2 = v; j2 = c;
            } else if (v > m3 || (v == m3 && c < j3)) {
                m3 = v; j3 = c;
            }
        }
        int c0i = j0;
        int c1i = (m0 - m1 <= TAU) ? j1 : j0;
        int c2i = (m0 - m2 <= TAU) ? j2 : j0;
        int c3i = (m0 - m3 <= TAU) ? j3 : j0;

        // serial ascending-k fp32 chains on EXACT residual (gmem re-read):
        // bitwise-replicates the reference accumulation; u = winner's value.
        const int n = n0 + tid;
        const int b = n / HW;
        const int hw = n - b * HW;
        const float* sp = src + (size_t)b * (CDIM * HW) + hw;
        const float4* p0 = (const float4*)(cb + (size_t)c0i * CDIM);
        const float4* p1 = (const float4*)(cb + (size_t)c1i * CDIM);
        const float4* p2 = (const float4*)(cb + (size_t)c2i * CDIM);
        const float4* p3 = (const float4*)(cb + (size_t)c3i * CDIM);
        float s0 = 0.0f, s1 = 0.0f, s2 = 0.0f, s3 = 0.0f;
#pragma unroll 4
        for (int q = 0; q < 64; q++) {
            float a0 = sp[(size_t)(q * 4 + 0) * HW];
            float a1 = sp[(size_t)(q * 4 + 1) * HW];
            float a2 = sp[(size_t)(q * 4 + 2) * HW];
            float a3 = sp[(size_t)(q * 4 + 3) * HW];
            float4 b0 = __ldg(p0 + q), b1 = __ldg(p1 + q);
            float4 b2 = __ldg(p2 + q), b3 = __ldg(p3 + q);
            s0 = fmaf(a0, b0.x, s0); s0 = fmaf(a1, b0.y, s0);
            s0 = fmaf(a2, b0.z, s0); s0 = fmaf(a3, b0.w, s0);
            s1 = fmaf(a0, b1.x, s1); s1 = fmaf(a1, b1.y, s1);
            s1 = fmaf(a2, b1.z, s1); s1 = fmaf(a3, b1.w, s1);
            s2 = fmaf(a0, b2.x, s2); s2 = fmaf(a1, b2.y, s2);
            s2 = fmaf(a2, b2.z, s2); s2 = fmaf(a3, b2.w, s2);
            s3 = fmaf(a0, b3.x, s3); s3 = fmaf(a1, b3.y, s3);
            s3 = fmaf(a2, b3.z, s3); s3 = fmaf(a3, b3.w, s3);
        }
        float bp = s0; int bi = c0i;
        if (s1 > bp || (s1 == bp && c1i < bi)) { bp = s1; bi = c1i; }
        if (s2 > bp || (s2 == bp && c2i < bi)) { bp = s2; bi = c2i; }
        if (s3 > bp || (s3 == bp && c3i < bi)) { bp = s3; bi = c3i; }
        scode[tid] = bi;
        su[tid]    = bp;
    }

    // ---- epilogue: resid = src - cb[code]*u  (mul then sub, exact) ----
    float* cbS = (float*)(smem + OFF_B);     // 32 x 257 floats
    for (int h = 0; h < 4; h++) {
        __syncthreads();
        for (int idx = tid; idx < 32 * 256; idx += NTH) {
            int rl = idx >> 8, c = idx & 255;
            cbS[rl * 257 + c] = cb[(size_t)scode[h * 32 + rl] * CDIM + c];
        }
        __syncthreads();
#pragma unroll 2
        for (int it = 0; it < 16; it++) {
            int idx = tid + it * NTH;
            int rl = idx & 31, c = idx >> 5;
            int r = h * 32 + rl;
            int n = n0 + r;
            int b = n / HW;
            int hw = n - b * HW;
            size_t gidx = (size_t)b * (CDIM * HW) + (size_t)c * HW + hw;
            float val = __fsub_rn(src[gidx],
                                  __fmul_rn(su[r], cbS[rl * 257 + c]));
            if (last) out[gidx] = __fsub_rn(x[gidx], val);
            else      g_resid[gidx] = val;
        }
    }
}

extern "C" void kernel_launch(void* const* d_in, const int* in_sizes, int n_in,
                              void* d_out, int out_size)
{
    const float* x  = (const float*)d_in[0];
    const float* cb = (const float*)d_in[1];
    float* out = (float*)d_out;

    cudaFuncSetAttribute(vq_step, cudaFuncAttributeMaxDynamicSharedMemorySize,
                         SMEM_BYTES);
    prep_cbt<<<1024, 256>>>(cb);
    dim3 grid(NROWS / TM), block(NTH);
    for (int it = 0; it < DEPTH; it++)
        vq_step<<<grid, block, SMEM_BYTES>>>(x, cb, out, it);
}

// round 12
// speedup vs baseline: 2.6105x; 1.2807x over previous
#include <cuda_runtime.h>
#include <cuda_fp16.h>
#include <cstdint>

// VQActivation depth-4 residual VQ.
// fp16 mma.sync ranking with fragment-packed smem + serial-fp32 rescoring
// that bitwise-matches the reference accumulation (decision layer exact).
#define CDIM  256
#define HW    3136
#define NROWS 100352
#define DEPTH 4
#define TM    128
#define NTH   512
#define TAU   0.008f

#define ASF_STRIDE 128                    // fp32 staging stride (floats)
#define A2_STRIDE  576                    // bytes per row (512 data + 64 pad)
#define OFF_CODE 0                        // 128 ints
#define OFF_SU   512                      // 128 floats
#define OFF_A2   1024
#define A2_BYTES (128*A2_STRIDE)          // 73728
#define OFF_B    (OFF_A2 + A2_BYTES)      // 74752
#define B_BYTES  8192                     // 128 codes x 32 halves; 3 buffers
#define OFF_ASF  (OFF_B + 3*B_BYTES)      // 99328
#define ASF_BYTES (CDIM*ASF_STRIDE*4)     // 131072  (256 chan x 128 rows)
#define OFF_RED  OFF_A2                   // reuse A2 after mainloop (73728 B)
#define SMEM_BYTES (OFF_ASF + ASF_BYTES)  // 230400  (< 232448 opt-in max)

__device__ float    g_resid[(size_t)NROWS * CDIM];
__device__ uint16_t g_cbh[1024 * 256];     // fp16 codebook, fragment-permuted

__device__ __forceinline__ void mma16(float* d, uint32_t a0, uint32_t a1,
                                      uint32_t a2, uint32_t a3,
                                      uint32_t b0, uint32_t b1) {
    asm volatile("mma.sync.aligned.m16n8k16.row.col.f32.f16.f16.f32 "
                 "{%0,%1,%2,%3}, {%4,%5,%6,%7}, {%8,%9}, {%0,%1,%2,%3};"
                 : "+f"(d[0]), "+f"(d[1]), "+f"(d[2]), "+f"(d[3])
                 : "r"(a0), "r"(a1), "r"(a2), "r"(a3), "r"(b0), "r"(b1));
}
#define CP16(sm, gp) asm volatile("cp.async.cg.shared.global [%0], [%1], 16;" :: "r"(sm), "l"(gp))
#define CP_COMMIT()  asm volatile("cp.async.commit_group;")
#define CP_WAIT1()   asm volatile("cp.async.wait_group 1;")
#define CP_WAIT0()   asm volatile("cp.async.wait_group 0;")
#define LDS128(r0,r1,r2,r3,addr) \
    asm volatile("ld.shared.v4.u32 {%0,%1,%2,%3}, [%4];" \
                 : "=r"(r0), "=r"(r1), "=r"(r2), "=r"(r3) : "r"(addr))

__device__ __forceinline__ uint32_t smem_u32(const void* p) {
    uint32_t a;
    asm("{ .reg .u64 t; cvta.to.shared.u64 t, %1; cvt.u32.u64 %0, t; }" : "=r"(a) : "l"(p));
    return a;
}

// packed half index p (0..255) -> original k:
//   qt=(p>>3)&3, j=p&7:  k = (p>>5)*32 + (j>>2)*16 + ((j>>1)&1)*8 + qt*2 + (j&1)
__global__ void prep_cbh(const float* __restrict__ cb) {
    int i = blockIdx.x * 256 + threadIdx.x;
    int p = i & 255, j = p & 7;
    int k = (p >> 5) * 32 + (j >> 2) * 16 + ((j >> 1) & 1) * 8
            + ((p >> 3) & 3) * 2 + (j & 1);
    g_cbh[i] = __half_as_ushort(__float2half_rn(cb[(i & ~255) + k]));
}

__global__ void __launch_bounds__(NTH, 1)
vq_step(const float* __restrict__ x, const float* __restrict__ cb,
        float* __restrict__ out, int iter)
{
    extern __shared__ char smem[];
    const uint32_t sb = smem_u32(smem);
    float*    AsF   = (float*)(smem + OFF_ASF);
    int*      scode = (int*)(smem + OFF_CODE);
    float*    su    = (float*)(smem + OFF_SU);

    const int tid  = threadIdx.x;
    const int lane = tid & 31, w = tid >> 5;
    const int quad = lane >> 2, qt = lane & 3;
    const int wr   = w >> 2;            // rows wr*32..+31
    const int wc   = w & 3;             // codes wc*32..+31 within tile
    const int wrow = wr * 32;
    const int n0   = blockIdx.x * TM;
    const float* src = (iter == 0) ? x : g_resid;
    const bool last = (iter == DEPTH - 1);

    auto prefetch = [&](int g, int buf) {   // chunk g: code tile g>>3, k-chunk g&7
        const uint16_t* gsrc = g_cbh
            + ((size_t)((g >> 3) * 128 + (tid >> 2)) << 8) + (g & 7) * 32 + (tid & 3) * 8;
        CP16(sb + OFF_B + (uint32_t)buf * B_BYTES + (tid >> 2) * 64 + (tid & 3) * 16,
             gsrc);
        CP_COMMIT();
    };
    prefetch(0, 0);
    prefetch(1, 1);

    // ---- stage exact fp32 A tile (coalesced; 256 chan x 128 rows) ----
    for (int idx = tid; idx < TM * CDIM; idx += NTH) {
        int c = idx >> 7, r = idx & 127;
        int n = n0 + r;
        int b = n / HW;
        int hw = n - b * HW;
        AsF[c * ASF_STRIDE + r] = src[(size_t)b * (CDIM * HW) + (size_t)c * HW + hw];
    }
    __syncthreads();

    // ---- repack A to fragment-ordered fp16 (A2) ----
    {
        int r = tid >> 2, q = tid & 3;
        uint32_t wbase = sb + OFF_A2 + r * A2_STRIDE + q * 16;
#pragma unroll
        for (int kc = 0; kc < 8; kc++)
#pragma unroll
            for (int jh = 0; jh < 4; jh++) {      // reg index within 16B frag
                int k0 = kc * 32 + (jh >> 1) * 16 + (jh & 1) * 8 + q * 2;
                __half h0 = __float2half_rn(AsF[k0 * ASF_STRIDE + r]);
                __half h1 = __float2half_rn(AsF[(k0 + 1) * ASF_STRIDE + r]);
                uint32_t v = (uint32_t)__half_as_ushort(h0)
                           | ((uint32_t)__half_as_ushort(h1) << 16);
                asm volatile("st.shared.u32 [%0], %1;"
                             :: "r"(wbase + kc * 64 + jh * 4), "r"(v));
            }
    }

    float mv[4][2]; int mi[4][2];
#pragma unroll
    for (int i = 0; i < 4; i++)
#pragma unroll
        for (int j = 0; j < 2; j++) { mv[i][j] = -3.0e38f; mi[i][j] = 0; }

    const uint32_t abase = sb + OFF_A2 + (wrow + quad) * A2_STRIDE + qt * 16;
    int buf = 0;
    for (int ct = 0; ct < 8; ct++) {
        float acc[8][4];
#pragma unroll
        for (int i = 0; i < 8; i++)
#pragma unroll
            for (int j = 0; j < 4; j++) acc[i][j] = 0.0f;

        for (int kc = 0; kc < 8; kc++) {
            int g = ct * 8 + kc;
            if (g == 63) CP_WAIT0(); else CP_WAIT1();
            __syncthreads();               // chunk g visible; buf (g+2)%3 free
            if (g + 2 < 64) {
                int nb = buf + 2; if (nb >= 3) nb -= 3;
                prefetch(g + 2, nb);
            }
            uint32_t Af[4][4], Bf[4][4];
            uint32_t ab = abase + kc * 64;
            LDS128(Af[0][0], Af[0][1], Af[0][2], Af[0][3], ab);
            LDS128(Af[1][0], Af[1][1], Af[1][2], Af[1][3], ab + 8  * A2_STRIDE);
            LDS128(Af[2][0], Af[2][1], Af[2][2], Af[2][3], ab + 16 * A2_STRIDE);
            LDS128(Af[3][0], Af[3][1], Af[3][2], Af[3][3], ab + 24 * A2_STRIDE);
            uint32_t bb = sb + OFF_B + (uint32_t)buf * B_BYTES
                        + (wc * 32 + quad) * 64 + qt * 16;
            LDS128(Bf[0][0], Bf[0][1], Bf[0][2], Bf[0][3], bb);
            LDS128(Bf[1][0], Bf[1][1], Bf[1][2], Bf[1][3], bb + 512);
            LDS128(Bf[2][0], Bf[2][1], Bf[2][2], Bf[2][3], bb + 1024);
            LDS128(Bf[3][0], Bf[3][1], Bf[3][2], Bf[3][3], bb + 1536);
#pragma unroll
            for (int s = 0; s < 2; s++)            // two k16 steps
#pragma unroll
                for (int half = 0; half < 2; half++)
#pragma unroll
                    for (int cf = 0; cf < 4; cf++)
                        mma16(acc[half * 4 + cf],
                              Af[half * 2][2 * s],     Af[half * 2 + 1][2 * s],
                              Af[half * 2][2 * s + 1], Af[half * 2 + 1][2 * s + 1],
                              Bf[cf][2 * s], Bf[cf][2 * s + 1]);
            buf++; if (buf >= 3) buf = 0;
        }

        // fold tile into per-thread top-2 (4 owned rows)
#pragma unroll
        for (int cf = 0; cf < 4; cf++)
#pragma unroll
            for (int half = 0; half < 2; half++)
#pragma unroll
                for (int j = 0; j < 4; j++) {
                    float v = acc[half * 4 + cf][j];
                    int lr = half * 2 + (j >> 1);
                    int code = ct * 128 + wc * 32 + cf * 8 + qt * 2 + (j & 1);
                    if (v > mv[lr][0]) {
                        mv[lr][1] = mv[lr][0]; mi[lr][1] = mi[lr][0];
                        mv[lr][0] = v;         mi[lr][0] = code;
                    } else if (v > mv[lr][1]) {
                        mv[lr][1] = v;         mi[lr][1] = code;
                    }
                }
    }

    // ---- merge: 16 partial top-2 sets per row (stride 33); reuses A2 ----
    float* redV = (float*)(smem + OFF_RED);
    int*   redI = (int*)(smem + OFF_RED + 16896);
    __syncthreads();                       // A2 dead from here on
    {
        int slot = wc * 4 + qt;
#pragma unroll
        for (int lr = 0; lr < 4; lr++) {
            int row = wrow + lr * 8 + quad;
            redV[row * 33 + slot * 2 + 0] = mv[lr][0];
            redV[row * 33 + slot * 2 + 1] = mv[lr][1];
            redI[row * 33 + slot * 2 + 0] = mi[lr][0];
            redI[row * 33 + slot * 2 + 1] = mi[lr][1];
        }
    }
    __syncthreads();

    if (tid < TM) {
        float m0 = -3.0e38f, m1 = -3.0e38f, m2 = -3.0e38f, m3 = -3.0e38f;
        int j0 = 0, j1 = 0, j2 = 0, j3 = 0;
#pragma unroll 2
        for (int s = 0; s < 32; s++) {
            float v = redV[tid * 33 + s];
            int   c = redI[tid * 33 + s];
            if (v > m0 || (v == m0 && c < j0)) {
                m3 = m2; j3 = j2; m2 = m1; j2 = j1; m1 = m0; j1 = j0; m0 = v; j0 = c;
            } else if (v > m1 || (v == m1 && c < j1)) {
                m3 = m2; j3 = j2; m2 = m1; j2 = j1; m1 = v; j1 = c;
            } else if (v > m2 || (v == m2 && c < j2)) {
                m3 = m2; j3 = j2; m2 = v; j2 = c;
            } else if (v > m3 || (v == m3 && c < j3)) {
                m3 = v; j3 = c;
            }
        }
        int c0i = j0;
        int c1i = (m0 - m1 <= TAU) ? j1 : j0;
        int c2i = (m0 - m2 <= TAU) ? j2 : j0;
        int c3i = (m0 - m3 <= TAU) ? j3 : j0;

        // serial ascending-k fp32 chains on EXACT residual (smem AsF):
        // bitwise-replicates the reference accumulation; u = winner's value.
        const float4* p0 = (const float4*)(cb + (size_t)c0i * CDIM);
        const float4* p1 = (const float4*)(cb + (size_t)c1i * CDIM);
        const float4* p2 = (const float4*)(cb + (size_t)c2i * CDIM);
        const float4* p3 = (const float4*)(cb + (size_t)c3i * CDIM);
        float s0 = 0.0f, s1 = 0.0f, s2 = 0.0f, s3 = 0.0f;
#pragma unroll 4
        for (int q = 0; q < 64; q++) {
            float a0 = AsF[(q * 4 + 0) * ASF_STRIDE + tid];
            float a1 = AsF[(q * 4 + 1) * ASF_STRIDE + tid];
            float a2 = AsF[(q * 4 + 2) * ASF_STRIDE + tid];
            float a3 = AsF[(q * 4 + 3) * ASF_STRIDE + tid];
            float4 b0 = __ldg(p0 + q), b1 = __ldg(p1 + q);
            float4 b2 = __ldg(p2 + q), b3 = __ldg(p3 + q);
            s0 = fmaf(a0, b0.x, s0); s0 = fmaf(a1, b0.y, s0);
            s0 = fmaf(a2, b0.z, s0); s0 = fmaf(a3, b0.w, s0);
            s1 = fmaf(a0, b1.x, s1); s1 = fmaf(a1, b1.y, s1);
            s1 = fmaf(a2, b1.z, s1); s1 = fmaf(a3, b1.w, s1);
            s2 = fmaf(a0, b2.x, s2); s2 = fmaf(a1, b2.y, s2);
            s2 = fmaf(a2, b2.z, s2); s2 = fmaf(a3, b2.w, s2);
            s3 = fmaf(a0, b3.x, s3); s3 = fmaf(a1, b3.y, s3);
            s3 = fmaf(a2, b3.z, s3); s3 = fmaf(a3, b3.w, s3);
        }
        float bp = s0; int bi = c0i;
        if (s1 > bp || (s1 == bp && c1i < bi)) { bp = s1; bi = c1i; }
        if (s2 > bp || (s2 == bp && c2i < bi)) { bp = s2; bi = c2i; }
        if (s3 > bp || (s3 == bp && c3i < bi)) { bp = s3; bi = c3i; }
        scode[tid] = bi;
        su[tid]    = bp;
    }

    // ---- epilogue: resid = AsF - cb[code]*u  (mul then sub, exact) ----
    float* cbS = (float*)(smem + OFF_RED);     // 32 x 257 floats, reuses A2
    for (int h = 0; h < 4; h++) {
        __syncthreads();
        for (int idx = tid; idx < 32 * 256; idx += NTH) {
            int rl = idx >> 8, c = idx & 255;
            cbS[rl * 257 + c] = cb[(size_t)scode[h * 32 + rl] * CDIM + c];
        }
        __syncthreads();
#pragma unroll 2
        for (int it = 0; it < 16; it++) {
            int idx = tid + it * NTH;
            int rl = idx & 31, c = idx >> 5;
            int r = h * 32 + rl;
            int n = n0 + r;
            int b = n / HW;
            int hw = n - b * HW;
            size_t gidx = (size_t)b * (CDIM * HW) + (size_t)c * HW + hw;
            float val = __fsub_rn(AsF[c * ASF_STRIDE + r],
                                  __fmul_rn(su[r], cbS[rl * 257 + c]));
            if (last) out[gidx] = __fsub_rn(x[gidx], val);
            else      g_resid[gidx] = val;
        }
    }
}

extern "C" void kernel_launch(void* const* d_in, const int* in_sizes, int n_in,
                              void* d_out, int out_size)
{
    const float* x  = (const float*)d_in[0];
    const float* cb = (const float*)d_in[1];
    float* out = (float*)d_out;

    cudaFuncSetAttribute(vq_step, cudaFuncAttributeMaxDynamicSharedMemorySize,
                         SMEM_BYTES);
    prep_cbh<<<1024, 256>>>(cb);
    dim3 grid(NROWS / TM), block(NTH);
    for (int it = 0; it < DEPTH; it++)
        vq_step<<<grid, block, SMEM_BYTES>>>(x, cb, out, it);
}

// round 14
// speedup vs baseline: 3.2863x; 1.2589x over previous
#include <cuda_runtime.h>
#include <cuda_fp16.h>
#include <cstdint>

// VQActivation depth-4 residual VQ.
// fp16 mma.sync ranking + serial-fp32 rescoring bitwise-matching the
// reference accumulation. 2 CTAs/SM (TM=64, 256 thr, 70.6KB smem) so the
// memory phases of one CTA overlap the latency-bound mainloop of the other.
#define CDIM  256
#define HW    3136
#define NROWS 100352
#define DEPTH 4
#define TM    64
#define NTH   256
#define TAU   0.008f

#define A2_STRIDE  576                    // bytes per row (512 data + 64 pad)
#define OFF_CODE 0                        // 64 ints
#define OFF_SU   256                      // 64 floats
#define OFF_A2   1024
#define A2_BYTES (64*A2_STRIDE)           // 36864
#define OFF_B    (OFF_A2 + A2_BYTES)      // 37888
#define B_BYTES  8192                     // 128 codes x 32 halves; 4 buffers
#define OFF_RED  OFF_A2                   // merge scratch / cbS reuse A2
#define SMEM_BYTES (OFF_B + 4*B_BYTES)    // 70656 -> 2 CTAs/SM (reg-limited)

__device__ float    g_resid[(size_t)NROWS * CDIM];
__device__ uint16_t g_cbh[1024 * 256];     // fp16 codebook, fragment-permuted

__device__ __forceinline__ void mma16(float* d, uint32_t a0, uint32_t a1,
                                      uint32_t a2, uint32_t a3,
                                      uint32_t b0, uint32_t b1) {
    asm volatile("mma.sync.aligned.m16n8k16.row.col.f32.f16.f16.f32 "
                 "{%0,%1,%2,%3}, {%4,%5,%6,%7}, {%8,%9}, {%0,%1,%2,%3};"
                 : "+f"(d[0]), "+f"(d[1]), "+f"(d[2]), "+f"(d[3])
                 : "r"(a0), "r"(a1), "r"(a2), "r"(a3), "r"(b0), "r"(b1));
}
#define CP16(sm, gp) asm volatile("cp.async.cg.shared.global [%0], [%1], 16;" :: "r"(sm), "l"(gp))
#define CP_COMMIT()  asm volatile("cp.async.commit_group;")
#define CP_WAIT2()   asm volatile("cp.async.wait_group 2;")
#define CP_WAIT1()   asm volatile("cp.async.wait_group 1;")
#define CP_WAIT0()   asm volatile("cp.async.wait_group 0;")
#define LDS128(r0,r1,r2,r3,addr) \
    asm volatile("ld.shared.v4.u32 {%0,%1,%2,%3}, [%4];" \
                 : "=r"(r0), "=r"(r1), "=r"(r2), "=r"(r3) : "r"(addr))

__device__ __forceinline__ uint32_t smem_u32(const void* p) {
    uint32_t a;
    asm("{ .reg .u64 t; cvta.to.shared.u64 t, %1; cvt.u32.u64 %0, t; }" : "=r"(a) : "l"(p));
    return a;
}

// packed half index p (0..255) -> original k:
//   qt=(p>>3)&3, j=p&7:  k = (p>>5)*32 + (j>>2)*16 + ((j>>1)&1)*8 + qt*2 + (j&1)
__global__ void prep_cbh(const float* __restrict__ cb) {
    int i = blockIdx.x * 256 + threadIdx.x;
    int p = i & 255, j = p & 7;
    int k = (p >> 5) * 32 + (j >> 2) * 16 + ((j >> 1) & 1) * 8
            + ((p >> 3) & 3) * 2 + (j & 1);
    g_cbh[i] = __half_as_ushort(__float2half_rn(cb[(i & ~255) + k]));
}

__global__ void __launch_bounds__(NTH, 2)
vq_step(const float* __restrict__ x, const float* __restrict__ cb,
        float* __restrict__ out, int iter)
{
    extern __shared__ char smem[];
    const uint32_t sb = smem_u32(smem);
    int*   scode = (int*)(smem + OFF_CODE);
    float* su    = (float*)(smem + OFF_SU);

    const int tid  = threadIdx.x;
    const int lane = tid & 31, w = tid >> 5;
    const int quad = lane >> 2, qt = lane & 3;
    const int wr   = w >> 2;            // rows wr*32..+31
    const int wc   = w & 3;             // codes wc*32..+31 within tile
    const int wrow = wr * 32;
    const int n0   = blockIdx.x * TM;
    const float* src = (iter == 0) ? x : g_resid;
    const bool last = (iter == DEPTH - 1);

    auto prefetch = [&](int g, int buf) {   // chunk g: code tile g>>3, k-chunk g&7
#pragma unroll
        for (int q = 0; q < 2; q++) {
            int j = tid + q * NTH;          // 0..511 fragment index
            int cl = j >> 2, qq = j & 3;
            CP16(sb + OFF_B + (uint32_t)buf * B_BYTES + cl * 64 + qq * 16,
                 g_cbh + ((size_t)((g >> 3) * 128 + cl) << 8) + (g & 7) * 32 + qq * 8);
        }
        CP_COMMIT();
    };
    prefetch(0, 0);
    prefetch(1, 1);
    prefetch(2, 2);

    // ---- stage: gmem fp32 -> fragment-packed fp16 A2 (direct) ----
    {
        int r = tid >> 2, q = tid & 3;      // row 0..63, frag quad-thread
        int n = n0 + r;
        int b = n / HW;
        int hw = n - b * HW;
        const float* sp = src + (size_t)b * (CDIM * HW) + hw;
        uint32_t wbase = sb + OFF_A2 + r * A2_STRIDE + q * 16;
#pragma unroll
        for (int kc = 0; kc < 8; kc++)
#pragma unroll
            for (int jh = 0; jh < 4; jh++) {
                int k0 = kc * 32 + (jh >> 1) * 16 + (jh & 1) * 8 + q * 2;
                __half h0 = __float2half_rn(sp[(size_t)k0 * HW]);
                __half h1 = __float2half_rn(sp[(size_t)(k0 + 1) * HW]);
                uint32_t v = (uint32_t)__half_as_ushort(h0)
                           | ((uint32_t)__half_as_ushort(h1) << 16);
                asm volatile("st.shared.u32 [%0], %1;"
                             :: "r"(wbase + kc * 64 + jh * 4), "r"(v));
            }
    }

    float mv[4][2]; int mi[4][2];
#pragma unroll
    for (int i = 0; i < 4; i++)
#pragma unroll
        for (int j = 0; j < 2; j++) { mv[i][j] = -3.0e38f; mi[i][j] = 0; }

    const uint32_t abase = sb + OFF_A2 + (wrow + quad) * A2_STRIDE + qt * 16;
    for (int ct = 0; ct < 8; ct++) {
        float acc[8][4];
#pragma unroll
        for (int i = 0; i < 8; i++)
#pragma unroll
            for (int j = 0; j < 4; j++) acc[i][j] = 0.0f;

#pragma unroll
        for (int kc = 0; kc < 8; kc++) {
            int g = ct * 8 + kc;
            if (g < 62) CP_WAIT2(); else if (g == 62) CP_WAIT1(); else CP_WAIT0();
            __syncthreads();               // chunk g visible; buf (g+3)&3 free
            if (g + 3 < 64) prefetch(g + 3, (g + 3) & 3);
            int buf = g & 3;
            uint32_t Af[4][4], Bf[4][4];
            uint32_t ab = abase + kc * 64;
            LDS128(Af[0][0], Af[0][1], Af[0][2], Af[0][3], ab);
            LDS128(Af[1][0], Af[1][1], Af[1][2], Af[1][3], ab + 8  * A2_STRIDE);
            LDS128(Af[2][0], Af[2][1], Af[2][2], Af[2][3], ab + 16 * A2_STRIDE);
            LDS128(Af[3][0], Af[3][1], Af[3][2], Af[3][3], ab + 24 * A2_STRIDE);
            uint32_t bb = sb + OFF_B + (uint32_t)buf * B_BYTES
                        + (wc * 32 + quad) * 64 + qt * 16;
            LDS128(Bf[0][0], Bf[0][1], Bf[0][2], Bf[0][3], bb);
            LDS128(Bf[1][0], Bf[1][1], Bf[1][2], Bf[1][3], bb + 512);
            LDS128(Bf[2][0], Bf[2][1], Bf[2][2], Bf[2][3], bb + 1024);
            LDS128(Bf[3][0], Bf[3][1], Bf[3][2], Bf[3][3], bb + 1536);
#pragma unroll
            for (int s = 0; s < 2; s++)            // two k16 steps
#pragma unroll
                for (int half = 0; half < 2; half++)
#pragma unroll
                    for (int cf = 0; cf < 4; cf++)
                        mma16(acc[half * 4 + cf],
                              Af[half * 2][2 * s],     Af[half * 2 + 1][2 * s],
                              Af[half * 2][2 * s + 1], Af[half * 2 + 1][2 * s + 1],
                              Bf[cf][2 * s], Bf[cf][2 * s + 1]);
        }

        // fold tile into per-thread top-2 (4 owned rows)
#pragma unroll
        for (int cf = 0; cf < 4; cf++)
#pragma unroll
            for (int half = 0; half < 2; half++)
#pragma unroll
                for (int j = 0; j < 4; j++) {
                    float v = acc[half * 4 + cf][j];
                    int lr = half * 2 + (j >> 1);
                    int code = ct * 128 + wc * 32 + cf * 8 + qt * 2 + (j & 1);
                    if (v > mv[lr][0]) {
                        mv[lr][1] = mv[lr][0]; mi[lr][1] = mi[lr][0];
                        mv[lr][0] = v;         mi[lr][0] = code;
                    } else if (v > mv[lr][1]) {
                        mv[lr][1] = v;         mi[lr][1] = code;
                    }
                }
    }

    // ---- merge: 16 partial top-2 sets per row (stride 33); reuses A2 ----
    float* redV = (float*)(smem + OFF_RED);
    int*   redI = (int*)(smem + OFF_RED + 8448);
    __syncthreads();                       // A2 dead from here on
    {
        int slot = wc * 4 + qt;
#pragma unroll
        for (int lr = 0; lr < 4; lr++) {
            int row = wrow + lr * 8 + quad;
            redV[row * 33 + slot * 2 + 0] = mv[lr][0];
            redV[row * 33 + slot * 2 + 1] = mv[lr][1];
            redI[row * 33 + slot * 2 + 0] = mi[lr][0];
            redI[row * 33 + slot * 2 + 1] = mi[lr][1];
        }
    }
    __syncthreads();

    if (tid < TM) {
        float m0 = -3.0e38f, m1 = -3.0e38f, m2 = -3.0e38f, m3 = -3.0e38f;
        int j0 = 0, j1 = 0, j2 = 0, j3 = 0;
#pragma unroll 2
        for (int s = 0; s < 32; s++) {
            float v = redV[tid * 33 + s];
            int   c = redI[tid * 33 + s];
            if (v > m0 || (v == m0 && c < j0)) {
                m3 = m2; j3 = j2; m2 = m1; j2 = j1; m1 = m0; j1 = j0; m0 = v; j0 = c;
            } else if (v > m1 || (v == m1 && c < j1)) {
                m3 = m2; j3 = j2; m2 = m1; j2 = j1; m1 = v; j1 = c;
            } else if (v > m2 || (v == m2 && c < j2)) {
                m3 = m2; j3 = j2; m2 = v; j2 = c;
            } else if (v > m3 || (v == m3 && c < j3)) {
                m3 = v; j3 = c;
            }
        }
        int c0i = j0;
        int c1i = (m0 - m1 <= TAU) ? j1 : j0;
        int c2i = (m0 - m2 <= TAU) ? j2 : j0;
        int c3i = (m0 - m3 <= TAU) ? j3 : j0;

        // serial ascending-k fp32 chains on EXACT residual (gmem re-read):
        // bitwise-replicates the reference accumulation; u = winner's value.
        const int n = n0 + tid;
        const int b = n / HW;
        const int hw = n - b * HW;
        const float* sp = src + (size_t)b * (CDIM * HW) + hw;
        const float4* p0 = (const float4*)(cb + (size_t)c0i * CDIM);
        const float4* p1 = (const float4*)(cb + (size_t)c1i * CDIM);
        const float4* p2 = (const float4*)(cb + (size_t)c2i * CDIM);
        const float4* p3 = (const float4*)(cb + (size_t)c3i * CDIM);
        float s0 = 0.0f, s1 = 0.0f, s2 = 0.0f, s3 = 0.0f;
#pragma unroll 4
        for (int q = 0; q < 64; q++) {
            float a0 = sp[(size_t)(q * 4 + 0) * HW];
            float a1 = sp[(size_t)(q * 4 + 1) * HW];
            float a2 = sp[(size_t)(q * 4 + 2) * HW];
            float a3 = sp[(size_t)(q * 4 + 3) * HW];
            float4 b0 = __ldg(p0 + q), b1 = __ldg(p1 + q);
            float4 b2 = __ldg(p2 + q), b3 = __ldg(p3 + q);
            s0 = fmaf(a0, b0.x, s0); s0 = fmaf(a1, b0.y, s0);
            s0 = fmaf(a2, b0.z, s0); s0 = fmaf(a3, b0.w, s0);
            s1 = fmaf(a0, b1.x, s1); s1 = fmaf(a1, b1.y, s1);
            s1 = fmaf(a2, b1.z, s1); s1 = fmaf(a3, b1.w, s1);
            s2 = fmaf(a0, b2.x, s2); s2 = fmaf(a1, b2.y, s2);
            s2 = fmaf(a2, b2.z, s2); s2 = fmaf(a3, b2.w, s2);
            s3 = fmaf(a0, b3.x, s3); s3 = fmaf(a1, b3.y, s3);
            s3 = fmaf(a2, b3.z, s3); s3 = fmaf(a3, b3.w, s3);
        }
        float bp = s0; int bi = c0i;
        if (s1 > bp || (s1 == bp && c1i < bi)) { bp = s1; bi = c1i; }
        if (s2 > bp || (s2 == bp && c2i < bi)) { bp = s2; bi = c2i; }
        if (s3 > bp || (s3 == bp && c3i < bi)) { bp = s3; bi = c3i; }
        scode[tid] = bi;
        su[tid]    = bp;
    }

    // ---- epilogue: resid = src - cb[code]*u  (mul then sub, exact) ----
    float* cbS = (float*)(smem + OFF_RED);     // 32 x 257 floats, reuses A2
    for (int h = 0; h < 2; h++) {              // rows [32h, 32h+32)
        __syncthreads();
        for (int idx = tid; idx < 32 * 256; idx += NTH) {
            int rl = idx >> 8, c = idx & 255;
            cbS[rl * 257 + c] = cb[(size_t)scode[h * 32 + rl] * CDIM + c];
        }
        __syncthreads();
#pragma unroll 4
        for (int it = 0; it < 32; it++) {
            int idx = tid + it * NTH;
            int rl = idx & 31, c = idx >> 5;
            int r = h * 32 + rl;
            int n = n0 + r;
            int b = n / HW;
            int hw = n - b * HW;
            size_t gidx = (size_t)b * (CDIM * HW) + (size_t)c * HW + hw;
            float val = __fsub_rn(src[gidx],
                                  __fmul_rn(su[r], cbS[rl * 257 + c]));
            if (last) out[gidx] = __fsub_rn(x[gidx], val);
            else      g_resid[gidx] = val;
        }
    }
}

extern "C" void kernel_launch(void* const* d_in, const int* in_sizes, int n_in,
                              void* d_out, int out_size)
{
    const float* x  = (const float*)d_in[0];
    const float* cb = (const float*)d_in[1];
    float* out = (float*)d_out;

    cudaFuncSetAttribute(vq_step, cudaFuncAttributeMaxDynamicSharedMemorySize,
                         SMEM_BYTES);
    prep_cbh<<<1024, 256>>>(cb);
    dim3 grid(NROWS / TM), block(NTH);
    for (int it = 0; it < DEPTH; it++)
        vq_step<<<grid, block, SMEM_BYTES>>>(x, cb, out, it);
}